// round 2
// baseline (speedup 1.0000x reference)
#include <cuda_runtime.h>
#include <stdint.h>

// MergedEmbSGD: merged multi-table EmbeddingBag, sum pooling.
// weights: [T, N, D] fp32
// indices: [T, BL]   int32 OR int64 (JAX x64-disabled downcasts; detect at runtime)
// offsets: [T, B]    same integer dtype as indices
// out:     [T, B, D] fp32
//
// One warp per bag. D=128 -> each lane owns one float4 (32 lanes * 4 floats).

#define D_DIM 128
#define D_VEC (D_DIM / 4)   // 32 float4 per row == one per lane

__device__ int g_idx_is_32;   // 1 if index/offset buffers are int32, 0 if int64

// Offsets per table are [0, L, 2L, ...] with L>0 (B>=2 bags).
// int32 view of an int64 buffer [0, L, ...] = [0, 0, L, 0, ...] -> elem 1 == 0.
// int32 buffer [0, L, 2L, ...]                                   -> elem 1 == L != 0.
__global__ void detect_dtype_kernel(const int* __restrict__ offs32)
{
    g_idx_is_32 = (offs32[1] != 0) ? 1 : 0;
}

template <typename IT>
__device__ __forceinline__ void embbag_body(
    const float4* __restrict__ w,
    const IT* __restrict__ idx,
    const IT* __restrict__ offs,
    float4* __restrict__ out,
    int T, long long N, int B, int BL,
    int warp_global, int lane)
{
    const int t = warp_global / B;
    const int b = warp_global - t * B;

    const long long off_base = (long long)t * B;
    const long long start = (long long)offs[off_base + b];
    const long long end   = (b + 1 < B) ? (long long)offs[off_base + b + 1]
                                        : (long long)BL;

    const IT*     __restrict__ idx_t = idx + (long long)t * BL;
    const float4* __restrict__ w_t   = w + (long long)t * N * D_VEC;

    float acc_x = 0.f, acc_y = 0.f, acc_z = 0.f, acc_w = 0.f;

    long long i = start;
    const long long n = end - start;

    if (n == 4) {
        // Fast path: pooling factor 4. Pre-read indices, issue 4 row loads
        // back-to-back for MLP.
        const long long r0 = (long long)idx_t[i + 0];
        const long long r1 = (long long)idx_t[i + 1];
        const long long r2 = (long long)idx_t[i + 2];
        const long long r3 = (long long)idx_t[i + 3];
        const float4 v0 = __ldg(&w_t[r0 * D_VEC + lane]);
        const float4 v1 = __ldg(&w_t[r1 * D_VEC + lane]);
        const float4 v2 = __ldg(&w_t[r2 * D_VEC + lane]);
        const float4 v3 = __ldg(&w_t[r3 * D_VEC + lane]);
        acc_x = (v0.x + v1.x) + (v2.x + v3.x);
        acc_y = (v0.y + v1.y) + (v2.y + v3.y);
        acc_z = (v0.z + v1.z) + (v2.z + v3.z);
        acc_w = (v0.w + v1.w) + (v2.w + v3.w);
    } else {
        for (; i + 2 <= end; i += 2) {
            const long long ra = (long long)idx_t[i];
            const long long rb = (long long)idx_t[i + 1];
            const float4 va = __ldg(&w_t[ra * D_VEC + lane]);
            const float4 vb = __ldg(&w_t[rb * D_VEC + lane]);
            acc_x += va.x + vb.x;
            acc_y += va.y + vb.y;
            acc_z += va.z + vb.z;
            acc_w += va.w + vb.w;
        }
        if (i < end) {
            const long long ra = (long long)idx_t[i];
            const float4 va = __ldg(&w_t[ra * D_VEC + lane]);
            acc_x += va.x; acc_y += va.y; acc_z += va.z; acc_w += va.w;
        }
    }

    float4 r;
    r.x = acc_x; r.y = acc_y; r.z = acc_z; r.w = acc_w;
    out[(long long)warp_global * D_VEC + lane] = r;
}

__global__ void __launch_bounds__(256, 8)
embbag_sum_kernel(const float4* __restrict__ w,
                  const void* __restrict__ idx_raw,
                  const void* __restrict__ offs_raw,
                  float4* __restrict__ out,
                  int T, long long N, int B, int BL)
{
    const int warp_global = (int)((blockIdx.x * (long long)blockDim.x + threadIdx.x) >> 5);
    const int lane = threadIdx.x & 31;
    if (warp_global >= T * B) return;

    if (g_idx_is_32) {
        embbag_body<int>(w, (const int*)idx_raw, (const int*)offs_raw,
                         out, T, N, B, BL, warp_global, lane);
    } else {
        embbag_body<long long>(w, (const long long*)idx_raw, (const long long*)offs_raw,
                               out, T, N, B, BL, warp_global, lane);
    }
}

extern "C" void kernel_launch(void* const* d_in, const int* in_sizes, int n_in,
                              void* d_out, int out_size)
{
    const float4* weights = (const float4*)d_in[0];
    const void*   indices = d_in[1];
    const void*   offsets = d_in[2];
    float4*       out     = (float4*)d_out;

    const int T = 26;
    const int B  = in_sizes[2] / T;                          // 16384
    const int BL = in_sizes[1] / T;                          // 65536
    const long long N = (long long)in_sizes[0] / ((long long)T * D_DIM); // 100000

    detect_dtype_kernel<<<1, 1>>>((const int*)offsets);

    const int total_bags = T * B;                  // 425984 warps
    const int threads = 256;                       // 8 warps/block
    const int warps_per_block = threads / 32;
    const int blocks = (total_bags + warps_per_block - 1) / warps_per_block;

    embbag_sum_kernel<<<blocks, threads>>>(weights, indices, offsets, out,
                                           T, N, B, BL);
}

// round 3
// speedup vs baseline: 1.1160x; 1.1160x over previous
#include <cuda_runtime.h>
#include <stdint.h>

// MergedEmbSGD: merged multi-table EmbeddingBag, sum pooling.
// weights: [T, N, D] fp32 ; indices/offsets int32 or int64 (runtime-detected)
// out: [T, B, D] fp32.  One warp per bag, persistent grid-stride.

#define D_DIM 128
#define D_VEC (D_DIM / 4)   // 32 float4 per row == one per lane

__device__ int g_idx_is_32;

// offsets per table = [0, L, 2L, ...], L>0.
// int32 view of int64 buffer -> elem 1 == 0 ; genuine int32 -> elem 1 == L != 0.
__global__ void detect_dtype_kernel(const int* __restrict__ offs32)
{
    g_idx_is_32 = (offs32[1] != 0) ? 1 : 0;
}

__device__ __forceinline__ void store_cs(float4* p, float4 v)
{
    asm volatile("st.global.cs.v4.f32 [%0], {%1,%2,%3,%4};"
                 :: "l"(p), "f"(v.x), "f"(v.y), "f"(v.z), "f"(v.w) : "memory");
}

// Load 4 consecutive indices starting at s (s % 4 == 0 guaranteed by caller).
__device__ __forceinline__ void load4idx(const int* p, long long s,
                                         long long& r0, long long& r1,
                                         long long& r2, long long& r3)
{
    int4 v = __ldg((const int4*)(p + s));
    r0 = v.x; r1 = v.y; r2 = v.z; r3 = v.w;
}
__device__ __forceinline__ void load4idx(const long long* p, long long s,
                                         long long& r0, long long& r1,
                                         long long& r2, long long& r3)
{
    longlong2 a = __ldg((const longlong2*)(p + s));
    longlong2 b = __ldg((const longlong2*)(p + s + 2));
    r0 = a.x; r1 = a.y; r2 = b.x; r3 = b.y;
}

template <typename IT>
__device__ __forceinline__ void run_bags(
    const float4* __restrict__ w,
    const IT* __restrict__ idx,
    const IT* __restrict__ offs,
    float4* __restrict__ out,
    int T, long long N, int B, int bshift, int BL, int total_bags,
    int warp, int nwarps, int lane)
{
    const long long wstride = N * D_VEC;   // float4 per table

    for (int bag = warp; bag < total_bags; bag += nwarps) {
        const int t = (bshift >= 0) ? (bag >> bshift) : (bag / B);
        const int b = bag - t * B;

        const IT* __restrict__ offs_t = offs + (long long)t * B;
        const long long start = (long long)offs_t[b];
        const long long end   = (b + 1 < B) ? (long long)offs_t[b + 1]
                                            : (long long)BL;

        const IT*     __restrict__ idx_t = idx + (long long)t * BL;
        const float4* __restrict__ w_t   = w + (long long)t * wstride;

        float4 acc; acc.x = 0.f; acc.y = 0.f; acc.z = 0.f; acc.w = 0.f;
        const long long n = end - start;

        if (n == 4 && ((start & 3) == 0)) {
            long long r0, r1, r2, r3;
            load4idx(idx_t, start, r0, r1, r2, r3);
            const float4 v0 = __ldg(w_t + r0 * D_VEC + lane);
            const float4 v1 = __ldg(w_t + r1 * D_VEC + lane);
            const float4 v2 = __ldg(w_t + r2 * D_VEC + lane);
            const float4 v3 = __ldg(w_t + r3 * D_VEC + lane);
            acc.x = (v0.x + v1.x) + (v2.x + v3.x);
            acc.y = (v0.y + v1.y) + (v2.y + v3.y);
            acc.z = (v0.z + v1.z) + (v2.z + v3.z);
            acc.w = (v0.w + v1.w) + (v2.w + v3.w);
        } else {
            for (long long i = start; i < end; ++i) {
                const long long r = (long long)idx_t[i];
                const float4 v = __ldg(w_t + r * D_VEC + lane);
                acc.x += v.x; acc.y += v.y; acc.z += v.z; acc.w += v.w;
            }
        }

        store_cs(out + (long long)bag * D_VEC + lane, acc);
    }
}

__global__ void __launch_bounds__(256, 8)
embbag_sum_kernel(const float4* __restrict__ w,
                  const void* __restrict__ idx_raw,
                  const void* __restrict__ offs_raw,
                  float4* __restrict__ out,
                  int T, long long N, int B, int bshift, int BL)
{
    const int lane  = threadIdx.x & 31;
    const int warp  = (int)((blockIdx.x * blockDim.x + threadIdx.x) >> 5);
    const int nwarps = (int)((gridDim.x * blockDim.x) >> 5);
    const int total_bags = T * B;

    if (g_idx_is_32) {
        run_bags<int>(w, (const int*)idx_raw, (const int*)offs_raw, out,
                      T, N, B, bshift, BL, total_bags, warp, nwarps, lane);
    } else {
        run_bags<long long>(w, (const long long*)idx_raw, (const long long*)offs_raw, out,
                            T, N, B, bshift, BL, total_bags, warp, nwarps, lane);
    }
}

extern "C" void kernel_launch(void* const* d_in, const int* in_sizes, int n_in,
                              void* d_out, int out_size)
{
    const float4* weights = (const float4*)d_in[0];
    const void*   indices = d_in[1];
    const void*   offsets = d_in[2];
    float4*       out     = (float4*)d_out;

    const int T = 26;
    const int B  = in_sizes[2] / T;                                   // 16384
    const int BL = in_sizes[1] / T;                                   // 65536
    const long long N = (long long)in_sizes[0] / ((long long)T * D_DIM); // 100000

    // power-of-two fast path for table id
    int bshift = -1;
    if ((B & (B - 1)) == 0) {
        bshift = 0;
        while ((1 << bshift) != B) bshift++;
    }

    detect_dtype_kernel<<<1, 1>>>((const int*)offsets);

    int sms = 148;
    cudaDeviceGetAttribute(&sms, cudaDevAttrMultiProcessorCount, 0);

    const int threads = 256;
    const int blocks  = sms * 8;   // persistent: exactly one wave at full occupancy

    embbag_sum_kernel<<<blocks, threads>>>(weights, indices, offsets, out,
                                           T, N, B, bshift, BL);
}

// round 4
// speedup vs baseline: 1.1401x; 1.0216x over previous
#include <cuda_runtime.h>
#include <stdint.h>

// MergedEmbSGD: merged multi-table EmbeddingBag, sum pooling.
// weights: [T, N, D] fp32 ; indices/offsets int32 or int64 (runtime-detected
// in-kernel: offsets per table = [0, L, 2L, ...]; int32 view of an int64
// buffer has elem 1 == 0, genuine int32 has elem 1 == L != 0).
// out: [T, B, D] fp32.  One warp per bag, persistent grid-stride, single kernel.

#define D_DIM 128
#define D_VEC (D_DIM / 4)   // 32 float4 per row == one per lane

__device__ __forceinline__ void store_cs(float4* p, float4 v)
{
    asm volatile("st.global.cs.v4.f32 [%0], {%1,%2,%3,%4};"
                 :: "l"(p), "f"(v.x), "f"(v.y), "f"(v.z), "f"(v.w) : "memory");
}

// Load 4 consecutive indices starting at s (caller guarantees s % 4 == 0).
__device__ __forceinline__ void load4idx(const int* p, long long s,
                                         long long& r0, long long& r1,
                                         long long& r2, long long& r3)
{
    int4 v = __ldg((const int4*)(p + s));
    r0 = v.x; r1 = v.y; r2 = v.z; r3 = v.w;
}
__device__ __forceinline__ void load4idx(const long long* p, long long s,
                                         long long& r0, long long& r1,
                                         long long& r2, long long& r3)
{
    longlong2 a = __ldg((const longlong2*)(p + s));
    longlong2 b = __ldg((const longlong2*)(p + s + 2));
    r0 = a.x; r1 = a.y; r2 = b.x; r3 = b.y;
}

template <typename IT>
__device__ __forceinline__ void run_bags(
    const float4* __restrict__ w,
    const IT* __restrict__ idx,
    const IT* __restrict__ offs,
    float4* __restrict__ out,
    int T, long long N, int B, int bshift, int BL, int total_bags,
    int warp, int nwarps, int lane)
{
    const long long wstride = N * D_VEC;   // float4 per table

    for (int bag = warp; bag < total_bags; bag += nwarps) {
        const int t = (bshift >= 0) ? (bag >> bshift) : (bag / B);
        const int b = bag - t * B;

        const IT* __restrict__ offs_t = offs + (long long)t * B;
        const long long start = (long long)offs_t[b];
        const long long end   = (b + 1 < B) ? (long long)offs_t[b + 1]
                                            : (long long)BL;

        const IT*     __restrict__ idx_t = idx + (long long)t * BL;
        const float4* __restrict__ w_t   = w + (long long)t * wstride;

        float4 acc; acc.x = 0.f; acc.y = 0.f; acc.z = 0.f; acc.w = 0.f;
        const long long n = end - start;

        if (n == 4 && ((start & 3) == 0)) {
            long long r0, r1, r2, r3;
            load4idx(idx_t, start, r0, r1, r2, r3);
            const float4 v0 = __ldg(w_t + r0 * D_VEC + lane);
            const float4 v1 = __ldg(w_t + r1 * D_VEC + lane);
            const float4 v2 = __ldg(w_t + r2 * D_VEC + lane);
            const float4 v3 = __ldg(w_t + r3 * D_VEC + lane);
            acc.x = (v0.x + v1.x) + (v2.x + v3.x);
            acc.y = (v0.y + v1.y) + (v2.y + v3.y);
            acc.z = (v0.z + v1.z) + (v2.z + v3.z);
            acc.w = (v0.w + v1.w) + (v2.w + v3.w);
        } else {
            for (long long i = start; i < end; ++i) {
                const long long r = (long long)idx_t[i];
                const float4 v = __ldg(w_t + r * D_VEC + lane);
                acc.x += v.x; acc.y += v.y; acc.z += v.z; acc.w += v.w;
            }
        }

        store_cs(out + (long long)bag * D_VEC + lane, acc);
    }
}

__global__ void __launch_bounds__(256, 8)
embbag_sum_kernel(const float4* __restrict__ w,
                  const void* __restrict__ idx_raw,
                  const void* __restrict__ offs_raw,
                  float4* __restrict__ out,
                  int T, long long N, int B, int bshift, int BL)
{
    const int lane   = threadIdx.x & 31;
    const int warp   = (int)((blockIdx.x * blockDim.x + threadIdx.x) >> 5);
    const int nwarps = (int)((gridDim.x * blockDim.x) >> 5);
    const int total_bags = T * B;

    // In-kernel dtype detection (uniform load, L2 broadcast; see header).
    const bool is32 = (__ldg((const int*)offs_raw + 1) != 0);

    if (is32) {
        run_bags<int>(w, (const int*)idx_raw, (const int*)offs_raw, out,
                      T, N, B, bshift, BL, total_bags, warp, nwarps, lane);
    } else {
        run_bags<long long>(w, (const long long*)idx_raw, (const long long*)offs_raw, out,
                            T, N, B, bshift, BL, total_bags, warp, nwarps, lane);
    }
}

extern "C" void kernel_launch(void* const* d_in, const int* in_sizes, int n_in,
                              void* d_out, int out_size)
{
    const float4* weights = (const float4*)d_in[0];
    const void*   indices = d_in[1];
    const void*   offsets = d_in[2];
    float4*       out     = (float4*)d_out;

    const int T = 26;
    const int B  = in_sizes[2] / T;                                   // 16384
    const int BL = in_sizes[1] / T;                                   // 65536
    const long long N = (long long)in_sizes[0] / ((long long)T * D_DIM); // 100000

    // power-of-two fast path for table id
    int bshift = -1;
    if ((B & (B - 1)) == 0) {
        bshift = 0;
        while ((1 << bshift) != B) bshift++;
    }

    int sms = 148;
    cudaDeviceGetAttribute(&sms, cudaDevAttrMultiProcessorCount, 0);

    const int threads = 256;
    const int blocks  = sms * 8;   // persistent: one full-occupancy wave

    embbag_sum_kernel<<<blocks, threads>>>(weights, indices, offsets, out,
                                           T, N, B, bshift, BL);
}